// round 3
// baseline (speedup 1.0000x reference)
#include <cuda_runtime.h>

#define BB 4
#define NT 2048
#define DD 512
#define HH 8
#define DHH 64
#define INNER 512
#define QKVC 1536
#define ATT_SCALE 0.125f

// Scratch (device globals — no cudaMalloc allowed)
static __device__ float g_qkv[(size_t)BB * NT * QKVC];   // 50.3 MB
static __device__ float g_obuf[(size_t)BB * NT * INNER]; // 16.8 MB

// ---------------------------------------------------------------------------
// SGEMM: C[M,Ncols] = A[M,K] @ Bm[K,Ncols] (+ bias). 128x128 tile, K-step 16,
// 256 threads, 8x8 micro-tile (2x2 of 4x4), double-buffered smem.
// ---------------------------------------------------------------------------
template <bool HAS_BIAS>
__global__ __launch_bounds__(256) void sgemm_kernel(
    const float* __restrict__ A, const float* __restrict__ Bm,
    const float* __restrict__ bias, float* __restrict__ C,
    int M, int Ncols, int K)
{
    __shared__ float As[2][16][132];   // k-major, m swizzled
    __shared__ float Bs[2][16][136];   // k-major, n natural

    const int tid = threadIdx.x;
    const int tx = tid & 15, ty = tid >> 4;
    const int m0 = blockIdx.y << 7, n0 = blockIdx.x << 7;

    const int am = tid >> 1;              // 0..127
    const int ak = (tid & 1) << 3;        // 0 or 8
    const int bk = tid >> 4;              // 0..15
    const int bn = (tid & 15) << 3;       // 0..120

    float acc[8][8] = {};
    float4 a0, a1, b0, b1;

    const float* Aptr = A + (size_t)(m0 + am) * K + ak;
    const float* Bptr = Bm + (size_t)bk * Ncols + n0 + bn;

    a0 = *(const float4*)(Aptr + 0);
    a1 = *(const float4*)(Aptr + 4);
    b0 = *(const float4*)(Bptr + 0);
    b1 = *(const float4*)(Bptr + 4);

#define STORE_TILE(buf)                                                     \
    do {                                                                    \
        As[buf][ak + 0][am ^ 0 ] = a0.x;                                    \
        As[buf][ak + 1][am ^ 4 ] = a0.y;                                    \
        As[buf][ak + 2][am ^ 8 ] = a0.z;                                    \
        As[buf][ak + 3][am ^ 12] = a0.w;                                    \
        As[buf][ak + 4][am ^ 16] = a1.x;                                    \
        As[buf][ak + 5][am ^ 20] = a1.y;                                    \
        As[buf][ak + 6][am ^ 24] = a1.z;                                    \
        As[buf][ak + 7][am ^ 28] = a1.w;                                    \
        *(float4*)&Bs[buf][bk][bn + 0] = b0;                                \
        *(float4*)&Bs[buf][bk][bn + 4] = b1;                                \
    } while (0)

    STORE_TILE(0);
    __syncthreads();

    const int nk = K >> 4;
    for (int t = 0; t < nk; t++) {
        const int buf = t & 1;
        if (t + 1 < nk) {
            const int k0 = (t + 1) << 4;
            a0 = *(const float4*)(Aptr + k0 + 0);
            a1 = *(const float4*)(Aptr + k0 + 4);
            b0 = *(const float4*)(Bptr + (size_t)k0 * Ncols + 0);
            b1 = *(const float4*)(Bptr + (size_t)k0 * Ncols + 4);
        }
#pragma unroll 4
        for (int kk = 0; kk < 16; kk++) {
            const int sw = (kk & 7) << 2;
            float av[8], bv[8];
            *(float4*)&av[0] = *(const float4*)&As[buf][kk][(ty << 2) ^ sw];
            *(float4*)&av[4] = *(const float4*)&As[buf][kk][64 + (((ty << 2)) ^ sw)];
            *(float4*)&bv[0] = *(const float4*)&Bs[buf][kk][tx << 2];
            *(float4*)&bv[4] = *(const float4*)&Bs[buf][kk][64 + (tx << 2)];
#pragma unroll
            for (int i = 0; i < 8; i++)
#pragma unroll
                for (int j = 0; j < 8; j++)
                    acc[i][j] = fmaf(av[i], bv[j], acc[i][j]);
        }
        if (t + 1 < nk) {
            const int nbuf = buf ^ 1;
            STORE_TILE(nbuf);
        }
        __syncthreads();
    }
#undef STORE_TILE

    float4 bias0 = make_float4(0.f, 0.f, 0.f, 0.f);
    float4 bias1 = make_float4(0.f, 0.f, 0.f, 0.f);
    if (HAS_BIAS) {
        bias0 = *(const float4*)(bias + n0 + (tx << 2));
        bias1 = *(const float4*)(bias + n0 + 64 + (tx << 2));
    }
#pragma unroll
    for (int i = 0; i < 8; i++) {
        const int mi = m0 + ((i < 4) ? ((ty << 2) + i) : (64 + (ty << 2) + i - 4));
        float4 o0, o1;
        o0.x = acc[i][0] + bias0.x; o0.y = acc[i][1] + bias0.y;
        o0.z = acc[i][2] + bias0.z; o0.w = acc[i][3] + bias0.w;
        o1.x = acc[i][4] + bias1.x; o1.y = acc[i][5] + bias1.y;
        o1.z = acc[i][6] + bias1.z; o1.w = acc[i][7] + bias1.w;
        *(float4*)(C + (size_t)mi * Ncols + n0 + (tx << 2)) = o0;
        *(float4*)(C + (size_t)mi * Ncols + n0 + 64 + (tx << 2)) = o1;
    }
}

// ---------------------------------------------------------------------------
// Fused flash attention with inline conv-bias.
// i-tile 128, j-tile 64, 256 threads.
// S loop: thread (ty,tx) -> rows ty*8..+7, cols tx*4..+3 (8x4 micro).
// PV loop: thread (ty,tx) -> rows ty*8..+7, d-cols tx*4..+3 (8x4 micro).
// All smem reads are float4 along the contiguous axis; Ks padded to 76 so the
// strided row-float4 reads are a perfect bank permutation.
// ---------------------------------------------------------------------------
#define QS(r, c) sm[(r) * 68 + (c)]
#define KS(r, c) sm[8704 + (r) * 76 + (c)]
#define VS(r, c) sm[13568 + (r) * 68 + (c)]
#define PS(r, c) sm[17920 + (r) * 68 + (c)]
#define ATTN_SMEM_FLOATS 26624

__global__ __launch_bounds__(256, 2) void attn_kernel(
    const float* __restrict__ qkv, const float* __restrict__ cd,
    const float* __restrict__ rel_w, const float* __restrict__ rel_b,
    float* __restrict__ obuf)
{
    extern __shared__ float sm[];

    const int tid = threadIdx.x;
    const int tx = tid & 15, ty = tid >> 4;
    const int h  = blockIdx.x & 7;           // h fastest -> cd L2 reuse
    const int i0 = (blockIdx.x >> 3) << 7;   // 128-row i tile
    const int b  = blockIdx.y;

    const float w0 = rel_w[h * 3 + 0], w1 = rel_w[h * 3 + 1], w2 = rel_w[h * 3 + 2];
    const float rb = rel_b[h];

    const size_t NN2 = (size_t)NT * NT;
    const float* cd0 = cd + (size_t)b * 3 * NN2;
    const float* cd1 = cd0 + NN2;
    const float* cd2 = cd0 + 2 * NN2;

    // Load Q tile [128][64] (natural layout, fully coalesced)
#pragma unroll
    for (int it = 0; it < 8; it++) {
        const int idx = tid + (it << 8);
        const int row = idx >> 4, d4 = (idx & 15) << 2;
        *(float4*)&QS(row, d4) =
            *(const float4*)(qkv + ((size_t)b * NT + i0 + row) * QKVC + h * DHH + d4);
    }

    float m_r[8], l_r[8], acc[8][4];
#pragma unroll
    for (int r = 0; r < 8; r++) {
        m_r[r] = -1e30f; l_r[r] = 0.f;
        acc[r][0] = acc[r][1] = acc[r][2] = acc[r][3] = 0.f;
    }

    for (int j0 = 0; j0 < NT; j0 += 64) {
        __syncthreads();  // previous iteration fully consumed K/V/P
        // Load K and V tiles [64][64]
#pragma unroll
        for (int it = 0; it < 4; it++) {
            const int idx = tid + (it << 8);
            const int row = idx >> 4, d4 = (idx & 15) << 2;
            const float* base = qkv + ((size_t)b * NT + j0 + row) * QKVC + h * DHH + d4;
            *(float4*)&KS(row, d4) = *(const float4*)(base + INNER);
            *(float4*)&VS(row, d4) = *(const float4*)(base + 2 * INNER);
        }
        __syncthreads();

        // S = Q K^T : 8x4 micro, float4 along d
        float s[8][4];
#pragma unroll
        for (int r = 0; r < 8; r++)
            s[r][0] = s[r][1] = s[r][2] = s[r][3] = 0.f;
#pragma unroll 2
        for (int d4 = 0; d4 < 64; d4 += 4) {
            float4 kv[4];
#pragma unroll
            for (int k = 0; k < 4; k++)
                kv[k] = *(const float4*)&KS((tx << 2) + k, d4);
#pragma unroll
            for (int r = 0; r < 8; r++) {
                const float4 qa = *(const float4*)&QS((ty << 3) + r, d4);
#pragma unroll
                for (int k = 0; k < 4; k++) {
                    s[r][k] = fmaf(qa.x, kv[k].x, s[r][k]);
                    s[r][k] = fmaf(qa.y, kv[k].y, s[r][k]);
                    s[r][k] = fmaf(qa.z, kv[k].z, s[r][k]);
                    s[r][k] = fmaf(qa.w, kv[k].w, s[r][k]);
                }
            }
        }

        // scale + conv1x1 bias + online softmax, write P
#pragma unroll
        for (int r = 0; r < 8; r++) {
            const size_t ro = (size_t)(i0 + (ty << 3) + r) * NT + j0 + (tx << 2);
            const float4 c0 = *(const float4*)(cd0 + ro);
            const float4 c1 = *(const float4*)(cd1 + ro);
            const float4 c2 = *(const float4*)(cd2 + ro);
            s[r][0] = fmaf(s[r][0], ATT_SCALE, w0 * c0.x + w1 * c1.x + w2 * c2.x + rb);
            s[r][1] = fmaf(s[r][1], ATT_SCALE, w0 * c0.y + w1 * c1.y + w2 * c2.y + rb);
            s[r][2] = fmaf(s[r][2], ATT_SCALE, w0 * c0.z + w1 * c1.z + w2 * c2.z + rb);
            s[r][3] = fmaf(s[r][3], ATT_SCALE, w0 * c0.w + w1 * c1.w + w2 * c2.w + rb);

            float mx = fmaxf(fmaxf(s[r][0], s[r][1]), fmaxf(s[r][2], s[r][3]));
#pragma unroll
            for (int off = 8; off > 0; off >>= 1)
                mx = fmaxf(mx, __shfl_xor_sync(0xffffffffu, mx, off));
            const float mnew = fmaxf(m_r[r], mx);
            const float fac = __expf(m_r[r] - mnew);
            m_r[r] = mnew;
            const float p0 = __expf(s[r][0] - mnew);
            const float p1 = __expf(s[r][1] - mnew);
            const float p2 = __expf(s[r][2] - mnew);
            const float p3 = __expf(s[r][3] - mnew);
            float rs = (p0 + p1) + (p2 + p3);
#pragma unroll
            for (int off = 8; off > 0; off >>= 1)
                rs += __shfl_xor_sync(0xffffffffu, rs, off);
            l_r[r] = l_r[r] * fac + rs;
            acc[r][0] *= fac; acc[r][1] *= fac; acc[r][2] *= fac; acc[r][3] *= fac;
            *(float4*)&PS((ty << 3) + r, tx << 2) = make_float4(p0, p1, p2, p3);
        }
        __syncthreads();

        // O += P V : 8x4 micro, float4 along d
#pragma unroll 2
        for (int jb = 0; jb < 64; jb += 4) {
            float4 vv[4];
#pragma unroll
            for (int k = 0; k < 4; k++)
                vv[k] = *(const float4*)&VS(jb + k, tx << 2);
#pragma unroll
            for (int r = 0; r < 8; r++) {
                const float4 p = *(const float4*)&PS((ty << 3) + r, jb);
                acc[r][0] = fmaf(p.x, vv[0].x, acc[r][0]);
                acc[r][1] = fmaf(p.x, vv[0].y, acc[r][1]);
                acc[r][2] = fmaf(p.x, vv[0].z, acc[r][2]);
                acc[r][3] = fmaf(p.x, vv[0].w, acc[r][3]);
                acc[r][0] = fmaf(p.y, vv[1].x, acc[r][0]);
                acc[r][1] = fmaf(p.y, vv[1].y, acc[r][1]);
                acc[r][2] = fmaf(p.y, vv[1].z, acc[r][2]);
                acc[r][3] = fmaf(p.y, vv[1].w, acc[r][3]);
                acc[r][0] = fmaf(p.z, vv[2].x, acc[r][0]);
                acc[r][1] = fmaf(p.z, vv[2].y, acc[r][1]);
                acc[r][2] = fmaf(p.z, vv[2].z, acc[r][2]);
                acc[r][3] = fmaf(p.z, vv[2].w, acc[r][3]);
                acc[r][0] = fmaf(p.w, vv[3].x, acc[r][0]);
                acc[r][1] = fmaf(p.w, vv[3].y, acc[r][1]);
                acc[r][2] = fmaf(p.w, vv[3].z, acc[r][2]);
                acc[r][3] = fmaf(p.w, vv[3].w, acc[r][3]);
            }
        }
    }

    // Normalize and write O into [B, N, h*64+d]
#pragma unroll
    for (int r = 0; r < 8; r++) {
        const float inv = 1.0f / l_r[r];
        float4 o = make_float4(acc[r][0] * inv, acc[r][1] * inv,
                               acc[r][2] * inv, acc[r][3] * inv);
        *(float4*)(obuf + ((size_t)b * NT + i0 + (ty << 3) + r) * INNER
                   + h * DHH + (tx << 2)) = o;
    }
}

// ---------------------------------------------------------------------------
extern "C" void kernel_launch(void* const* d_in, const int* in_sizes, int n_in,
                              void* d_out, int out_size)
{
    const float* x     = (const float*)d_in[0];
    const float* cd    = (const float*)d_in[1];
    const float* Wqkv  = (const float*)d_in[2];
    const float* Wout  = (const float*)d_in[3];
    const float* bout  = (const float*)d_in[4];
    const float* rel_w = (const float*)d_in[5];
    const float* rel_b = (const float*)d_in[6];
    float* out = (float*)d_out;

    float *qkvb = nullptr, *obuf = nullptr;
    cudaGetSymbolAddress((void**)&qkvb, g_qkv);
    cudaGetSymbolAddress((void**)&obuf, g_obuf);

    const int ATTN_SMEM = ATTN_SMEM_FLOATS * (int)sizeof(float);  // 106496 B
    cudaFuncSetAttribute(attn_kernel, cudaFuncAttributeMaxDynamicSharedMemorySize,
                         ATTN_SMEM);

    dim3 blk(256);
    // qkv = x @ Wqkv : [8192,512] x [512,1536]
    sgemm_kernel<false><<<dim3(QKVC / 128, (BB * NT) / 128), blk>>>(
        x, Wqkv, nullptr, qkvb, BB * NT, QKVC, DD);
    // fused attention
    attn_kernel<<<dim3(HH * (NT / 128), BB), blk, ATTN_SMEM>>>(
        qkvb, cd, rel_w, rel_b, obuf);
    // out = obuf @ Wout + bout : [8192,512] x [512,512]
    sgemm_kernel<true><<<dim3(DD / 128, (BB * NT) / 128), blk>>>(
        obuf, Wout, bout, out, BB * NT, DD, DD);
}

// round 4
// speedup vs baseline: 1.2949x; 1.2949x over previous
#include <cuda_runtime.h>
#include <cstdint>

#define BB 4
#define NT 2048
#define DD 512
#define HH 8
#define DHH 64
#define INNER 512
#define QKVC 1536
#define ATT_SCALE 0.125f
#define NJT 32            // 2048/64 j-tiles

// Scratch (device globals — no cudaMalloc allowed)
static __device__ float g_qkv[(size_t)BB * NT * QKVC];   // 50.3 MB (tf32-rounded)
static __device__ float g_obuf[(size_t)BB * NT * INNER]; // 16.8 MB

// ---------------------------------------------------------------------------
// helpers
// ---------------------------------------------------------------------------
__device__ __forceinline__ uint32_t f2tf32(float x) {
    uint32_t r;
    asm("cvt.rna.tf32.f32 %0, %1;" : "=r"(r) : "f"(x));
    return r;
}

__device__ __forceinline__ uint32_t smaddr(const void* p) {
    uint32_t a;
    asm("{.reg .u64 t; cvta.to.shared.u64 t, %1; cvt.u32.u64 %0, t;}"
        : "=r"(a) : "l"(p));
    return a;
}

__device__ __forceinline__ void mma_tf32(float c[4], uint32_t a0, uint32_t a1,
                                         uint32_t a2, uint32_t a3,
                                         uint32_t b0, uint32_t b1) {
    asm volatile(
        "mma.sync.aligned.m16n8k8.row.col.f32.tf32.tf32.f32 "
        "{%0,%1,%2,%3}, {%4,%5,%6,%7}, {%8,%9}, {%0,%1,%2,%3};"
        : "+f"(c[0]), "+f"(c[1]), "+f"(c[2]), "+f"(c[3])
        : "r"(a0), "r"(a1), "r"(a2), "r"(a3), "r"(b0), "r"(b1));
}

__device__ __forceinline__ void bulk_cp(uint32_t dst, const void* src,
                                        uint32_t mbar) {
    asm volatile(
        "cp.async.bulk.shared::cta.global.mbarrier::complete_tx::bytes "
        "[%0], [%1], %2, [%3];"
        :: "r"(dst), "l"(src), "r"(256u), "r"(mbar) : "memory");
}

__device__ __forceinline__ void mbar_expect(uint32_t mbar, uint32_t bytes) {
    asm volatile("mbarrier.arrive.expect_tx.shared.b64 _, [%0], %1;"
                 :: "r"(mbar), "r"(bytes) : "memory");
}

__device__ __forceinline__ void mbar_wait(uint32_t mbar, uint32_t parity) {
    uint32_t done;
    do {
        asm volatile(
            "{.reg .pred p; "
            "mbarrier.try_wait.parity.acquire.cta.shared::cta.b64 p, [%1], %2, 0x989680; "
            "selp.b32 %0,1,0,p;}"
            : "=r"(done) : "r"(mbar), "r"(parity) : "memory");
    } while (!done);
}

// ---------------------------------------------------------------------------
// SGEMM (R1 version, proven): 64x64 tile, K-step 16, 256 thr, 4x4 micro.
// TFR: round outputs to tf32 (rna) for downstream tensor-core consumption.
// ---------------------------------------------------------------------------
template <bool HAS_BIAS, bool TFR>
__global__ __launch_bounds__(256) void sgemm_kernel(
    const float* __restrict__ A, const float* __restrict__ Bm,
    const float* __restrict__ bias, float* __restrict__ C,
    int M, int Ncols, int K)
{
    __shared__ float As[16][68];
    __shared__ float Bs[16][68];
    const int tid = threadIdx.x;
    const int tx = tid & 15, ty = tid >> 4;
    const int m0 = blockIdx.y << 6, n0 = blockIdx.x << 6;
    const int ar = tid >> 2, ac4 = (tid & 3) << 2;
    const int bkr = tid >> 4, bc = (tid & 15) << 2;

    float acc[4][4] = {};

    for (int k0 = 0; k0 < K; k0 += 16) {
        float4 a = *(const float4*)(A + (size_t)(m0 + ar) * K + (k0 + ac4));
        As[ac4 + 0][ar] = a.x;
        As[ac4 + 1][ar] = a.y;
        As[ac4 + 2][ar] = a.z;
        As[ac4 + 3][ar] = a.w;
        *(float4*)&Bs[bkr][bc] =
            *(const float4*)(Bm + (size_t)(k0 + bkr) * Ncols + (n0 + bc));
        __syncthreads();
#pragma unroll
        for (int kk = 0; kk < 16; kk++) {
            float av[4], bv[4];
            *(float4*)av = *(const float4*)&As[kk][ty << 2];
            *(float4*)bv = *(const float4*)&Bs[kk][tx << 2];
#pragma unroll
            for (int i = 0; i < 4; i++)
#pragma unroll
                for (int j = 0; j < 4; j++)
                    acc[i][j] = fmaf(av[i], bv[j], acc[i][j]);
        }
        __syncthreads();
    }

    float4 bv4 = make_float4(0.f, 0.f, 0.f, 0.f);
    if (HAS_BIAS) bv4 = *(const float4*)(bias + n0 + (tx << 2));
#pragma unroll
    for (int i = 0; i < 4; i++) {
        float4 o;
        o.x = acc[i][0] + bv4.x;
        o.y = acc[i][1] + bv4.y;
        o.z = acc[i][2] + bv4.z;
        o.w = acc[i][3] + bv4.w;
        if (TFR) {
            o.x = __uint_as_float(f2tf32(o.x));
            o.y = __uint_as_float(f2tf32(o.y));
            o.z = __uint_as_float(f2tf32(o.z));
            o.w = __uint_as_float(f2tf32(o.w));
        }
        *(float4*)(C + (size_t)(m0 + (ty << 2) + i) * Ncols + n0 + (tx << 2)) = o;
    }
}

// ---------------------------------------------------------------------------
// Fused flash attention, tf32 tensor cores + bulk-async staging.
// Block: 256 thr (8 warps). i-tile 128 (warp w owns rows w*16..+15, all 64 j).
// smem (floats):
//   QF  [8 wtile][8 kk][128]        A-fragments of Q       (32 KB)
//   KS  [64][68] raw K tile                                 (17 KB)
//   VS  [64][68] raw V tile                                 (17 KB)
//   CD  [3][128][68] raw centroid_delta tile               (102 KB)
//   PS  [8 w][16][68] raw P (tf32 bits)                     (34 KB)
//   mbar (8 B)
// ---------------------------------------------------------------------------
#define QF0 0
#define KS0 8192
#define VS0 12544
#define CD0 16896
#define PS0 43008
#define SM_FLOATS 51712
#define ATTN_SMEM_BYTES (SM_FLOATS * 4 + 16)

__device__ __forceinline__ void issue_rowA(int idx, int jn0, int b, int h,
                                           int i0, const float* qkv,
                                           const float* cd, float* sm,
                                           uint32_t mbar) {
    // idx in [0,448): 0..63 -> K rows, 64..447 -> cd rows
    if (idx < 64) {
        const float* src = qkv + ((size_t)(b * NT + jn0 + idx) * QKVC
                                  + INNER + h * DHH);
        bulk_cp(smaddr(sm + KS0 + idx * 68), src, mbar);
    } else {
        const int p = (idx - 64) >> 7, rl = (idx - 64) & 127;
        const float* src = cd + ((size_t)(b * 3 + p) * NT * NT
                                 + (size_t)(i0 + rl) * NT + jn0);
        bulk_cp(smaddr(sm + CD0 + (p * 128 + rl) * 68), src, mbar);
    }
}

__global__ __launch_bounds__(256) void attn_kernel(
    const float* __restrict__ qkv, const float* __restrict__ cd,
    const float* __restrict__ rel_w, const float* __restrict__ rel_b,
    float* __restrict__ obuf)
{
    extern __shared__ float sm[];
    const int tid = threadIdx.x;
    const int lane = tid & 31, w = tid >> 5;
    const int g = lane >> 2, t = lane & 3;
    const int h = blockIdx.x & 7;
    const int i0 = (blockIdx.x >> 3) << 7;
    const int b = blockIdx.y;

    const uint32_t mbar = smaddr(sm + SM_FLOATS);

    if (tid == 0) {
        asm volatile("mbarrier.init.shared.b64 [%0], %1;"
                     :: "r"(mbar), "r"(512u) : "memory");
        asm volatile("fence.proxy.async.shared::cta;" ::: "memory");
    }
    __syncthreads();

    // ---- prologue: issue copies for j-tile 0 (2 expect_tx per thread) ----
    {
        const uint32_t bytesA = (tid < 192) ? 512u : 256u;
        mbar_expect(mbar, bytesA);
        issue_rowA(tid, 0, b, h, i0, qkv, cd, sm, mbar);
        if (tid < 192) issue_rowA(tid + 256, 0, b, h, i0, qkv, cd, sm, mbar);
        mbar_expect(mbar, (tid < 64) ? 256u : 0u);
        if (tid < 64) {
            const float* src = qkv + ((size_t)(b * NT + tid) * QKVC
                                      + 2 * INNER + h * DHH);
            bulk_cp(smaddr(sm + VS0 + tid * 68), src, mbar);
        }
    }

    // ---- stage Q into A-fragment layout (values already tf32-rounded) ----
#pragma unroll
    for (int it = 0; it < 8; it++) {
        const int rowl = (tid >> 4) + it * 16;      // 0..127
        const int d4 = (tid & 15) << 2;
        float4 v = *(const float4*)(qkv + ((size_t)(b * NT + i0 + rowl) * QKVC
                                           + h * DHH + d4));
        const int wq = rowl >> 4, r16 = rowl & 15;
        const int gq = r16 & 7, hi = r16 >> 3;
        const float vv[4] = {v.x, v.y, v.z, v.w};
#pragma unroll
        for (int e = 0; e < 4; e++) {
            const int d = d4 + e;
            const int kk = d >> 3, tt = d & 3, shi = (d >> 2) & 1;
            sm[QF0 + ((wq * 8 + kk) << 7) + ((gq * 4 + tt) << 2) + hi + 2 * shi]
                = vv[e];
        }
    }
    __syncthreads();   // QF ready for all warps

    const float w0 = rel_w[h * 3 + 0], w1 = rel_w[h * 3 + 1], w2 = rel_w[h * 3 + 2];
    const float rb = rel_b[h];

    float m0 = -1e30f, m1 = -1e30f, l0 = 0.f, l1 = 0.f;
    float o[8][4];
#pragma unroll
    for (int dd = 0; dd < 8; dd++)
        o[dd][0] = o[dd][1] = o[dd][2] = o[dd][3] = 0.f;

    const float* PSw = sm + PS0 + w * (16 * 68);
    float* PSwm = sm + PS0 + w * (16 * 68);

    for (int jt = 0; jt < NJT; jt++) {
        mbar_wait(mbar, jt & 1);

        // ---- S = Q K^T (tf32 mma) ----
        float s_[8][4];
#pragma unroll
        for (int nn = 0; nn < 8; nn++)
            s_[nn][0] = s_[nn][1] = s_[nn][2] = s_[nn][3] = 0.f;
#pragma unroll
        for (int kk = 0; kk < 8; kk++) {
            const uint4 a = *(const uint4*)&sm[QF0 + ((w * 8 + kk) << 7) + (lane << 2)];
#pragma unroll
            for (int nn = 0; nn < 8; nn++) {
                const uint32_t b0 = __float_as_uint(sm[KS0 + (nn * 8 + g) * 68 + kk * 8 + t]);
                const uint32_t b1 = __float_as_uint(sm[KS0 + (nn * 8 + g) * 68 + kk * 8 + t + 4]);
                mma_tf32(s_[nn], a.x, a.y, a.z, a.w, b0, b1);
            }
        }

        // ---- bias + online softmax + P store (tf32) ----
        const int rl0 = w * 16 + g, rl1 = rl0 + 8;
        float mx0 = -1e30f, mx1 = -1e30f;
#pragma unroll
        for (int nn = 0; nn < 8; nn++) {
            const int c = nn * 8 + 2 * t;
            const float2 p00 = *(const float2*)&sm[CD0 + rl0 * 68 + c];
            const float2 p01 = *(const float2*)&sm[CD0 + 8704 + rl0 * 68 + c];
            const float2 p02 = *(const float2*)&sm[CD0 + 17408 + rl0 * 68 + c];
            const float2 p10 = *(const float2*)&sm[CD0 + rl1 * 68 + c];
            const float2 p11 = *(const float2*)&sm[CD0 + 8704 + rl1 * 68 + c];
            const float2 p12 = *(const float2*)&sm[CD0 + 17408 + rl1 * 68 + c];
            s_[nn][0] = fmaf(s_[nn][0], ATT_SCALE, w0 * p00.x + w1 * p01.x + w2 * p02.x + rb);
            s_[nn][1] = fmaf(s_[nn][1], ATT_SCALE, w0 * p00.y + w1 * p01.y + w2 * p02.y + rb);
            s_[nn][2] = fmaf(s_[nn][2], ATT_SCALE, w0 * p10.x + w1 * p11.x + w2 * p12.x + rb);
            s_[nn][3] = fmaf(s_[nn][3], ATT_SCALE, w0 * p10.y + w1 * p11.y + w2 * p12.y + rb);
            mx0 = fmaxf(mx0, fmaxf(s_[nn][0], s_[nn][1]));
            mx1 = fmaxf(mx1, fmaxf(s_[nn][2], s_[nn][3]));
        }
#pragma unroll
        for (int off = 1; off <= 2; off <<= 1) {
            mx0 = fmaxf(mx0, __shfl_xor_sync(0xffffffffu, mx0, off));
            mx1 = fmaxf(mx1, __shfl_xor_sync(0xffffffffu, mx1, off));
        }
        const float mn0 = fmaxf(m0, mx0), mn1 = fmaxf(m1, mx1);
        const float fac0 = __expf(m0 - mn0), fac1 = __expf(m1 - mn1);
        m0 = mn0; m1 = mn1;
        float rs0 = 0.f, rs1 = 0.f;
#pragma unroll
        for (int nn = 0; nn < 8; nn++) {
            const float e0 = __expf(s_[nn][0] - mn0);
            const float e1 = __expf(s_[nn][1] - mn0);
            const float e2 = __expf(s_[nn][2] - mn1);
            const float e3 = __expf(s_[nn][3] - mn1);
            rs0 += e0 + e1; rs1 += e2 + e3;
            const int c = nn * 8 + 2 * t;
            *(uint2*)&PSwm[g * 68 + c] = make_uint2(f2tf32(e0), f2tf32(e1));
            *(uint2*)&PSwm[(g + 8) * 68 + c] = make_uint2(f2tf32(e2), f2tf32(e3));
        }
#pragma unroll
        for (int off = 1; off <= 2; off <<= 1) {
            rs0 += __shfl_xor_sync(0xffffffffu, rs0, off);
            rs1 += __shfl_xor_sync(0xffffffffu, rs1, off);
        }
        l0 = l0 * fac0 + rs0;
        l1 = l1 * fac1 + rs1;
#pragma unroll
        for (int dd = 0; dd < 8; dd++) {
            o[dd][0] *= fac0; o[dd][1] *= fac0;
            o[dd][2] *= fac1; o[dd][3] *= fac1;
        }

        __syncthreads();   // point A: KS + CD fully consumed; PS visible in warp

        if (jt + 1 < NJT) {
            const int jn = (jt + 1) * 64;
            mbar_expect(mbar, (tid < 192) ? 512u : 256u);
            issue_rowA(tid, jn, b, h, i0, qkv, cd, sm, mbar);
            if (tid < 192) issue_rowA(tid + 256, jn, b, h, i0, qkv, cd, sm, mbar);
        }

        // ---- O += P V (tf32 mma) ----
#pragma unroll
        for (int jj = 0; jj < 8; jj++) {
            const uint32_t a0 = __float_as_uint(PSw[g * 68 + jj * 8 + t]);
            const uint32_t a1 = __float_as_uint(PSw[(g + 8) * 68 + jj * 8 + t]);
            const uint32_t a2 = __float_as_uint(PSw[g * 68 + jj * 8 + t + 4]);
            const uint32_t a3 = __float_as_uint(PSw[(g + 8) * 68 + jj * 8 + t + 4]);
#pragma unroll
            for (int dd = 0; dd < 8; dd++) {
                const uint32_t b0 = __float_as_uint(sm[VS0 + (jj * 8 + t) * 68 + dd * 8 + g]);
                const uint32_t b1 = __float_as_uint(sm[VS0 + (jj * 8 + t + 4) * 68 + dd * 8 + g]);
                mma_tf32(o[dd], a0, a1, a2, a3, b0, b1);
            }
        }

        __syncthreads();   // point B: VS fully consumed

        if (jt + 1 < NJT) {
            const int jn = (jt + 1) * 64;
            mbar_expect(mbar, (tid < 64) ? 256u : 0u);
            if (tid < 64) {
                const float* src = qkv + ((size_t)(b * NT + jn + tid) * QKVC
                                          + 2 * INNER + h * DHH);
                bulk_cp(smaddr(sm + VS0 + tid * 68), src, mbar);
            }
        }
    }

    // ---- normalize + write O [b, i, h*64+d] ----
    const float inv0 = 1.0f / l0, inv1 = 1.0f / l1;
    const int row0 = i0 + w * 16 + g, row1 = row0 + 8;
#pragma unroll
    for (int dd = 0; dd < 8; dd++) {
        const int col = h * DHH + dd * 8 + 2 * t;
        *(float2*)(obuf + (size_t)(b * NT + row0) * INNER + col) =
            make_float2(o[dd][0] * inv0, o[dd][1] * inv0);
        *(float2*)(obuf + (size_t)(b * NT + row1) * INNER + col) =
            make_float2(o[dd][2] * inv1, o[dd][3] * inv1);
    }
}

// ---------------------------------------------------------------------------
extern "C" void kernel_launch(void* const* d_in, const int* in_sizes, int n_in,
                              void* d_out, int out_size)
{
    const float* x     = (const float*)d_in[0];
    const float* cd    = (const float*)d_in[1];
    const float* Wqkv  = (const float*)d_in[2];
    const float* Wout  = (const float*)d_in[3];
    const float* bout  = (const float*)d_in[4];
    const float* rel_w = (const float*)d_in[5];
    const float* rel_b = (const float*)d_in[6];
    float* out = (float*)d_out;

    float *qkvb = nullptr, *obuf = nullptr;
    cudaGetSymbolAddress((void**)&qkvb, g_qkv);
    cudaGetSymbolAddress((void**)&obuf, g_obuf);

    cudaFuncSetAttribute(attn_kernel, cudaFuncAttributeMaxDynamicSharedMemorySize,
                         ATTN_SMEM_BYTES);

    dim3 blk(256);
    // qkv = x @ Wqkv : [8192,512] x [512,1536], outputs tf32-rounded
    sgemm_kernel<false, true><<<dim3(QKVC / 64, (BB * NT) / 64), blk>>>(
        x, Wqkv, nullptr, qkvb, BB * NT, QKVC, DD);
    // fused attention (h fastest in grid.x for cd L2 reuse)
    attn_kernel<<<dim3(HH * (NT / 128), BB), blk, ATTN_SMEM_BYTES>>>(
        qkvb, cd, rel_w, rel_b, obuf);
    // out = obuf @ Wout + bout : [8192,512] x [512,512], full fp32
    sgemm_kernel<true, false><<<dim3(DD / 64, (BB * NT) / 64), blk>>>(
        obuf, Wout, bout, out, BB * NT, DD, DD);
}